// round 2
// baseline (speedup 1.0000x reference)
#include <cuda_runtime.h>

#define N_NODES 50000
#define N_EDGES 600000
#define IN_DIM  128
#define HID     256

// ---------------- device scratch (no allocation allowed) ----------------
__device__ int   g_count[N_NODES];
__device__ int   g_fill[N_NODES];
__device__ int   g_rowptr[N_NODES + 1];
__device__ float g_dinv[N_NODES];
__device__ int   g_col[N_EDGES];
__device__ float g_w[N_EDGES];
__device__ float g_xagg[(size_t)N_NODES * IN_DIM];
__device__ float g_h1[(size_t)N_NODES * HID];
__device__ float g_h1agg[(size_t)N_NODES * HID];
__device__ float g_h2[(size_t)N_NODES * HID];

// ---------------- preprocessing ----------------
__global__ void k_zero() {
    int i = blockIdx.x * blockDim.x + threadIdx.x;
    if (i < N_NODES) { g_count[i] = 0; g_fill[i] = 0; }
}

__global__ void k_hist(const int* __restrict__ dst) {
    int e = blockIdx.x * blockDim.x + threadIdx.x;
    if (e < N_EDGES) atomicAdd(&g_count[dst[e]], 1);
}

__global__ void k_dinv() {
    int i = blockIdx.x * blockDim.x + threadIdx.x;
    if (i < N_NODES) g_dinv[i] = rsqrtf((float)g_count[i] + 1.0f);
}

// single-block chunked exclusive scan of g_count -> g_rowptr
__global__ void k_scan() {
    __shared__ int sh[1024];
    int carry = 0;
    for (int base = 0; base < N_NODES; base += 1024) {
        int i = base + threadIdx.x;
        int v = (i < N_NODES) ? g_count[i] : 0;
        sh[threadIdx.x] = v;
        __syncthreads();
        for (int off = 1; off < 1024; off <<= 1) {
            int t = (threadIdx.x >= off) ? sh[threadIdx.x - off] : 0;
            __syncthreads();
            sh[threadIdx.x] += t;
            __syncthreads();
        }
        int incl = sh[threadIdx.x];
        if (i < N_NODES) g_rowptr[i] = carry + incl - v;
        carry += sh[1023];
        __syncthreads();
    }
    if (threadIdx.x == 0) g_rowptr[N_NODES] = carry;
}

__global__ void k_sort(const int* __restrict__ src, const int* __restrict__ dst) {
    int e = blockIdx.x * blockDim.x + threadIdx.x;
    if (e >= N_EDGES) return;
    int d = dst[e];
    int s = src[e];
    int pos = g_rowptr[d] + atomicAdd(&g_fill[d], 1);
    g_col[pos] = s;
    g_w[pos]   = g_dinv[s];
}

// ---------------- aggregation: out[n] = dinv[n]*(sum_p w[p]*in[col[p]] + dinv[n]*in[n]) ----------------
template <int F>
__global__ void k_agg(const float* __restrict__ in, float* __restrict__ out) {
    int gwarp = (blockIdx.x * blockDim.x + threadIdx.x) >> 5;
    int lane  = threadIdx.x & 31;
    if (gwarp >= N_NODES) return;
    int beg = g_rowptr[gwarp];
    int end = g_rowptr[gwarp + 1];
    float dn = g_dinv[gwarp];
    constexpr int V = F / 128;   // float4s per lane
    float4 acc[V];
#pragma unroll
    for (int v = 0; v < V; v++) acc[v] = make_float4(0.f, 0.f, 0.f, 0.f);
    for (int p = beg; p < end; p++) {
        int s   = g_col[p];
        float w = g_w[p];
        const float4* rp = (const float4*)(in + (size_t)s * F);
#pragma unroll
        for (int v = 0; v < V; v++) {
            float4 t = rp[lane + 32 * v];
            acc[v].x += w * t.x; acc[v].y += w * t.y;
            acc[v].z += w * t.z; acc[v].w += w * t.w;
        }
    }
    const float4* sp = (const float4*)(in + (size_t)gwarp * F);
    float4* op = (float4*)(out + (size_t)gwarp * F);
#pragma unroll
    for (int v = 0; v < V; v++) {
        float4 t = sp[lane + 32 * v];
        float4 r;
        r.x = dn * (acc[v].x + dn * t.x);
        r.y = dn * (acc[v].y + dn * t.y);
        r.z = dn * (acc[v].z + dn * t.z);
        r.w = dn * (acc[v].w + dn * t.w);
        op[lane + 32 * v] = r;
    }
}

// ---------------- SGEMM: C[M,256] = act(A[M,K] @ W[K,256] + b) ----------------
// BM=128, BN=128, BK=8, 256 threads, 8x8 per thread (4+4 split layout)
template <int K, bool RELU>
__global__ void __launch_bounds__(256, 2)
k_gemm(const float* __restrict__ A, const float* __restrict__ W,
       const float* __restrict__ bias, float* __restrict__ C, int M) {
    __shared__ float As[8][128];
    __shared__ float Bs[8][128];
    const int bm = blockIdx.x * 128;
    const int bn = blockIdx.y * 128;
    const int tid = threadIdx.x;
    const int tx = tid % 16;   // column group
    const int ty = tid / 16;   // row group

    // A loads: 128 rows x 8 k, 2 threads per row x float4
    const int a_r = tid >> 1;
    const int a_c = (tid & 1) * 4;
    // B loads: 8 k rows x 128 cols, 32 threads per row x float4
    const int b_r = tid >> 5;
    const int b_c = (tid & 31) * 4;

    float acc[8][8];
#pragma unroll
    for (int i = 0; i < 8; i++)
#pragma unroll
        for (int j = 0; j < 8; j++) acc[i][j] = 0.f;

    for (int k0 = 0; k0 < K; k0 += 8) {
        float4 av = make_float4(0.f, 0.f, 0.f, 0.f);
        int m = bm + a_r;
        if (m < M) av = *(const float4*)(A + (size_t)m * K + k0 + a_c);
        As[a_c + 0][a_r] = av.x;
        As[a_c + 1][a_r] = av.y;
        As[a_c + 2][a_r] = av.z;
        As[a_c + 3][a_r] = av.w;
        *(float4*)&Bs[b_r][b_c] =
            *(const float4*)(W + (size_t)(k0 + b_r) * 256 + bn + b_c);
        __syncthreads();
#pragma unroll
        for (int kk = 0; kk < 8; kk++) {
            float a[8], b[8];
            float4 t;
            t = *(const float4*)&As[kk][ty * 4];
            a[0] = t.x; a[1] = t.y; a[2] = t.z; a[3] = t.w;
            t = *(const float4*)&As[kk][64 + ty * 4];
            a[4] = t.x; a[5] = t.y; a[6] = t.z; a[7] = t.w;
            t = *(const float4*)&Bs[kk][tx * 4];
            b[0] = t.x; b[1] = t.y; b[2] = t.z; b[3] = t.w;
            t = *(const float4*)&Bs[kk][64 + tx * 4];
            b[4] = t.x; b[5] = t.y; b[6] = t.z; b[7] = t.w;
#pragma unroll
            for (int i = 0; i < 8; i++)
#pragma unroll
                for (int j = 0; j < 8; j++) acc[i][j] += a[i] * b[j];
        }
        __syncthreads();
    }

    // epilogue
#pragma unroll
    for (int i = 0; i < 8; i++) {
        int r = bm + ((i < 4) ? (ty * 4 + i) : (64 + ty * 4 + (i - 4)));
        if (r >= M) continue;
#pragma unroll
        for (int jh = 0; jh < 2; jh++) {
            int c0 = bn + ((jh == 0) ? (tx * 4) : (64 + tx * 4));
            float4 v;
            float* a4 = &acc[i][jh * 4];
            v.x = a4[0] + bias[c0 + 0];
            v.y = a4[1] + bias[c0 + 1];
            v.z = a4[2] + bias[c0 + 2];
            v.w = a4[3] + bias[c0 + 3];
            if (RELU) {
                v.x = fmaxf(v.x, 0.f); v.y = fmaxf(v.y, 0.f);
                v.z = fmaxf(v.z, 0.f); v.w = fmaxf(v.w, 0.f);
            }
            *(float4*)(C + (size_t)r * 256 + c0) = v;
        }
    }
}

// ---------------- final projection: out[N,2] = h2 @ Wl + bl ----------------
__global__ void k_out(const float* __restrict__ h2, const float* __restrict__ Wl,
                      const float* __restrict__ bl, float* __restrict__ out) {
    int gwarp = (blockIdx.x * blockDim.x + threadIdx.x) >> 5;
    int lane  = threadIdx.x & 31;
    if (gwarp >= N_NODES) return;
    const float4* rp = (const float4*)(h2 + (size_t)gwarp * HID);
    float s0 = 0.f, s1 = 0.f;
#pragma unroll
    for (int v = 0; v < 2; v++) {
        float4 t = rp[lane + 32 * v];
        int k = (lane + 32 * v) * 4;
        s0 += t.x * Wl[(k + 0) * 2 + 0] + t.y * Wl[(k + 1) * 2 + 0]
            + t.z * Wl[(k + 2) * 2 + 0] + t.w * Wl[(k + 3) * 2 + 0];
        s1 += t.x * Wl[(k + 0) * 2 + 1] + t.y * Wl[(k + 1) * 2 + 1]
            + t.z * Wl[(k + 2) * 2 + 1] + t.w * Wl[(k + 3) * 2 + 1];
    }
#pragma unroll
    for (int off = 16; off > 0; off >>= 1) {
        s0 += __shfl_down_sync(0xFFFFFFFFu, s0, off);
        s1 += __shfl_down_sync(0xFFFFFFFFu, s1, off);
    }
    if (lane == 0) {
        out[(size_t)gwarp * 2 + 0] = s0 + bl[0];
        out[(size_t)gwarp * 2 + 1] = s1 + bl[1];
    }
}

// ---------------- launch ----------------
extern "C" void kernel_launch(void* const* d_in, const int* in_sizes, int n_in,
                              void* d_out, int out_size) {
    const float* x   = (const float*)d_in[0];
    const int*   ei  = (const int*)d_in[1];
    const float* W1  = (const float*)d_in[2];
    const float* b1  = (const float*)d_in[3];
    const float* W2  = (const float*)d_in[4];
    const float* b2  = (const float*)d_in[5];
    const float* Wl  = (const float*)d_in[6];
    const float* bl  = (const float*)d_in[7];
    float* out = (float*)d_out;

    const int* src = ei;            // edge_index[0, :]
    const int* dst = ei + N_EDGES;  // edge_index[1, :]

    float* xagg;  cudaGetSymbolAddress((void**)&xagg,  g_xagg);
    float* h1;    cudaGetSymbolAddress((void**)&h1,    g_h1);
    float* h1agg; cudaGetSymbolAddress((void**)&h1agg, g_h1agg);
    float* h2;    cudaGetSymbolAddress((void**)&h2,    g_h2);

    const int TB = 256;
    k_zero<<<(N_NODES + TB - 1) / TB, TB>>>();
    k_hist<<<(N_EDGES + TB - 1) / TB, TB>>>(dst);
    k_dinv<<<(N_NODES + TB - 1) / TB, TB>>>();
    k_scan<<<1, 1024>>>();
    k_sort<<<(N_EDGES + TB - 1) / TB, TB>>>(src, dst);

    // layer 1: aggregate 128-d input first (linearity), then GEMM+bias+relu
    {
        int warps = N_NODES;
        int blocks = (warps * 32 + TB - 1) / TB;
        k_agg<IN_DIM><<<blocks, TB>>>(x, xagg);
    }
    {
        dim3 grid((N_NODES + 127) / 128, 2);
        k_gemm<IN_DIM, true><<<grid, 256>>>(xagg, W1, b1, h1, N_NODES);
    }
    // layer 2
    {
        int warps = N_NODES;
        int blocks = (warps * 32 + TB - 1) / TB;
        k_agg<HID><<<blocks, TB>>>(h1, h1agg);
    }
    {
        dim3 grid((N_NODES + 127) / 128, 2);
        k_gemm<HID, true><<<grid, 256>>>(h1agg, W2, b2, h2, N_NODES);
    }
    // output projection
    {
        int blocks = (N_NODES * 32 + TB - 1) / TB;
        k_out<<<blocks, TB>>>(h2, Wl, bl, out);
    }
}

// round 3
// speedup vs baseline: 1.7140x; 1.7140x over previous
#include <cuda_runtime.h>

#define N_NODES 50000
#define N_EDGES 600000
#define IN_DIM  128
#define HID     256

#define SCAN_B  1024
#define NBLK    ((N_NODES + SCAN_B - 1) / SCAN_B)   // 49

// ---------------- device scratch (no allocation allowed) ----------------
__device__ int   g_count[N_NODES];
__device__ int   g_fill[N_NODES];
__device__ int   g_rowptr[N_NODES + 1];
__device__ int   g_bsum[NBLK];
__device__ int   g_boff[NBLK];
__device__ float g_dinv[N_NODES];
__device__ int   g_col[N_EDGES];
__device__ float g_w[N_EDGES];
__device__ float g_xagg[(size_t)N_NODES * IN_DIM];
__device__ float g_h1[(size_t)N_NODES * HID];
__device__ float g_h1agg[(size_t)N_NODES * HID];
__device__ float g_h2[(size_t)N_NODES * HID];

// ---------------- preprocessing ----------------
__global__ void k_zero() {
    int i = blockIdx.x * blockDim.x + threadIdx.x;
    if (i < N_NODES) { g_count[i] = 0; g_fill[i] = 0; }
}

__global__ void k_hist(const int* __restrict__ dst) {
    int e = blockIdx.x * blockDim.x + threadIdx.x;
    if (e < N_EDGES) atomicAdd(&g_count[dst[e]], 1);
}

__global__ void k_dinv() {
    int i = blockIdx.x * blockDim.x + threadIdx.x;
    if (i < N_NODES) g_dinv[i] = rsqrtf((float)g_count[i] + 1.0f);
}

// ---- parallel exclusive scan of g_count -> g_rowptr (3 phases) ----
__global__ void k_scan1() {
    __shared__ int warpsums[32];
    int b = blockIdx.x;
    int i = b * SCAN_B + threadIdx.x;
    int v = (i < N_NODES) ? g_count[i] : 0;
    int lane = threadIdx.x & 31, w = threadIdx.x >> 5;
    // warp inclusive scan
    int p = v;
#pragma unroll
    for (int off = 1; off < 32; off <<= 1) {
        int t = __shfl_up_sync(0xFFFFFFFFu, p, off);
        if (lane >= off) p += t;
    }
    if (lane == 31) warpsums[w] = p;
    __syncthreads();
    if (w == 0) {
        int s = warpsums[lane];
#pragma unroll
        for (int off = 1; off < 32; off <<= 1) {
            int t = __shfl_up_sync(0xFFFFFFFFu, s, off);
            if (lane >= off) s += t;
        }
        warpsums[lane] = s;
    }
    __syncthreads();
    int excl = p - v + (w > 0 ? warpsums[w - 1] : 0);
    if (i < N_NODES) g_rowptr[i] = excl;
    if (threadIdx.x == SCAN_B - 1) g_bsum[b] = excl + v;
}

__global__ void k_scan2() {
    if (threadIdx.x == 0) {
        int acc = 0;
#pragma unroll
        for (int b = 0; b < NBLK; b++) { g_boff[b] = acc; acc += g_bsum[b]; }
        g_rowptr[N_NODES] = acc;
    }
}

__global__ void k_scan3() {
    int i = blockIdx.x * blockDim.x + threadIdx.x;
    if (i < N_NODES) g_rowptr[i] += g_boff[i >> 10];
}

__global__ void k_sort(const int* __restrict__ src, const int* __restrict__ dst) {
    int e = blockIdx.x * blockDim.x + threadIdx.x;
    if (e >= N_EDGES) return;
    int d = dst[e];
    int s = src[e];
    int pos = g_rowptr[d] + atomicAdd(&g_fill[d], 1);
    g_col[pos] = s;
    g_w[pos]   = g_dinv[s];
}

// ---------------- aggregation: out[n] = dinv[n]*(sum_p w[p]*in[col[p]] + dinv[n]*in[n]) ----------------
template <int F>
__global__ void k_agg(const float* __restrict__ in, float* __restrict__ out) {
    int gwarp = (blockIdx.x * blockDim.x + threadIdx.x) >> 5;
    int lane  = threadIdx.x & 31;
    if (gwarp >= N_NODES) return;
    int beg = g_rowptr[gwarp];
    int end = g_rowptr[gwarp + 1];
    float dn = g_dinv[gwarp];
    constexpr int V = F / 128;   // float4s per lane
    float4 acc[V];
#pragma unroll
    for (int v = 0; v < V; v++) acc[v] = make_float4(0.f, 0.f, 0.f, 0.f);
    for (int p = beg; p < end; p++) {
        int s   = g_col[p];
        float w = g_w[p];
        const float4* rp = (const float4*)(in + (size_t)s * F);
#pragma unroll
        for (int v = 0; v < V; v++) {
            float4 t = rp[lane + 32 * v];
            acc[v].x += w * t.x; acc[v].y += w * t.y;
            acc[v].z += w * t.z; acc[v].w += w * t.w;
        }
    }
    const float4* sp = (const float4*)(in + (size_t)gwarp * F);
    float4* op = (float4*)(out + (size_t)gwarp * F);
#pragma unroll
    for (int v = 0; v < V; v++) {
        float4 t = sp[lane + 32 * v];
        float4 r;
        r.x = dn * (acc[v].x + dn * t.x);
        r.y = dn * (acc[v].y + dn * t.y);
        r.z = dn * (acc[v].z + dn * t.z);
        r.w = dn * (acc[v].w + dn * t.w);
        op[lane + 32 * v] = r;
    }
}

// ---------------- SGEMM: C[M,256] = act(A[M,K] @ W[K,256] + b) ----------------
// BM=128, BN=128, BK=8, 256 threads, 8x8 per thread (4+4 split layout)
template <int K, bool RELU>
__global__ void __launch_bounds__(256, 2)
k_gemm(const float* __restrict__ A, const float* __restrict__ W,
       const float* __restrict__ bias, float* __restrict__ C, int M) {
    __shared__ float As[8][128];
    __shared__ float Bs[8][128];
    const int bm = blockIdx.x * 128;
    const int bn = blockIdx.y * 128;
    const int tid = threadIdx.x;
    const int tx = tid % 16;   // column group
    const int ty = tid / 16;   // row group

    const int a_r = tid >> 1;
    const int a_c = (tid & 1) * 4;
    const int b_r = tid >> 5;
    const int b_c = (tid & 31) * 4;

    float acc[8][8];
#pragma unroll
    for (int i = 0; i < 8; i++)
#pragma unroll
        for (int j = 0; j < 8; j++) acc[i][j] = 0.f;

    for (int k0 = 0; k0 < K; k0 += 8) {
        float4 av = make_float4(0.f, 0.f, 0.f, 0.f);
        int m = bm + a_r;
        if (m < M) av = *(const float4*)(A + (size_t)m * K + k0 + a_c);
        As[a_c + 0][a_r] = av.x;
        As[a_c + 1][a_r] = av.y;
        As[a_c + 2][a_r] = av.z;
        As[a_c + 3][a_r] = av.w;
        *(float4*)&Bs[b_r][b_c] =
            *(const float4*)(W + (size_t)(k0 + b_r) * 256 + bn + b_c);
        __syncthreads();
#pragma unroll
        for (int kk = 0; kk < 8; kk++) {
            float a[8], b[8];
            float4 t;
            t = *(const float4*)&As[kk][ty * 4];
            a[0] = t.x; a[1] = t.y; a[2] = t.z; a[3] = t.w;
            t = *(const float4*)&As[kk][64 + ty * 4];
            a[4] = t.x; a[5] = t.y; a[6] = t.z; a[7] = t.w;
            t = *(const float4*)&Bs[kk][tx * 4];
            b[0] = t.x; b[1] = t.y; b[2] = t.z; b[3] = t.w;
            t = *(const float4*)&Bs[kk][64 + tx * 4];
            b[4] = t.x; b[5] = t.y; b[6] = t.z; b[7] = t.w;
#pragma unroll
            for (int i = 0; i < 8; i++)
#pragma unroll
                for (int j = 0; j < 8; j++) acc[i][j] += a[i] * b[j];
        }
        __syncthreads();
    }

#pragma unroll
    for (int i = 0; i < 8; i++) {
        int r = bm + ((i < 4) ? (ty * 4 + i) : (64 + ty * 4 + (i - 4)));
        if (r >= M) continue;
#pragma unroll
        for (int jh = 0; jh < 2; jh++) {
            int c0 = bn + ((jh == 0) ? (tx * 4) : (64 + tx * 4));
            float4 v;
            float* a4 = &acc[i][jh * 4];
            v.x = a4[0] + bias[c0 + 0];
            v.y = a4[1] + bias[c0 + 1];
            v.z = a4[2] + bias[c0 + 2];
            v.w = a4[3] + bias[c0 + 3];
            if (RELU) {
                v.x = fmaxf(v.x, 0.f); v.y = fmaxf(v.y, 0.f);
                v.z = fmaxf(v.z, 0.f); v.w = fmaxf(v.w, 0.f);
            }
            *(float4*)(C + (size_t)r * 256 + c0) = v;
        }
    }
}

// ---------------- final projection: out[N,2] = h2 @ Wl + bl ----------------
__global__ void k_out(const float* __restrict__ h2, const float* __restrict__ Wl,
                      const float* __restrict__ bl, float* __restrict__ out) {
    int gwarp = (blockIdx.x * blockDim.x + threadIdx.x) >> 5;
    int lane  = threadIdx.x & 31;
    if (gwarp >= N_NODES) return;
    const float4* rp = (const float4*)(h2 + (size_t)gwarp * HID);
    float s0 = 0.f, s1 = 0.f;
#pragma unroll
    for (int v = 0; v < 2; v++) {
        float4 t = rp[lane + 32 * v];
        int k = (lane + 32 * v) * 4;
        s0 += t.x * Wl[(k + 0) * 2 + 0] + t.y * Wl[(k + 1) * 2 + 0]
            + t.z * Wl[(k + 2) * 2 + 0] + t.w * Wl[(k + 3) * 2 + 0];
        s1 += t.x * Wl[(k + 0) * 2 + 1] + t.y * Wl[(k + 1) * 2 + 1]
            + t.z * Wl[(k + 2) * 2 + 1] + t.w * Wl[(k + 3) * 2 + 1];
    }
#pragma unroll
    for (int off = 16; off > 0; off >>= 1) {
        s0 += __shfl_down_sync(0xFFFFFFFFu, s0, off);
        s1 += __shfl_down_sync(0xFFFFFFFFu, s1, off);
    }
    if (lane == 0) {
        out[(size_t)gwarp * 2 + 0] = s0 + bl[0];
        out[(size_t)gwarp * 2 + 1] = s1 + bl[1];
    }
}

// ---------------- launch ----------------
extern "C" void kernel_launch(void* const* d_in, const int* in_sizes, int n_in,
                              void* d_out, int out_size) {
    const float* x   = (const float*)d_in[0];
    const int*   ei  = (const int*)d_in[1];
    const float* W1  = (const float*)d_in[2];
    const float* b1  = (const float*)d_in[3];
    const float* W2  = (const float*)d_in[4];
    const float* b2  = (const float*)d_in[5];
    const float* Wl  = (const float*)d_in[6];
    const float* bl  = (const float*)d_in[7];
    float* out = (float*)d_out;

    const int* src = ei;            // edge_index[0, :]
    const int* dst = ei + N_EDGES;  // edge_index[1, :]

    float* xagg;  cudaGetSymbolAddress((void**)&xagg,  g_xagg);
    float* h1;    cudaGetSymbolAddress((void**)&h1,    g_h1);
    float* h1agg; cudaGetSymbolAddress((void**)&h1agg, g_h1agg);
    float* h2;    cudaGetSymbolAddress((void**)&h2,    g_h2);

    const int TB = 256;
    k_zero<<<(N_NODES + TB - 1) / TB, TB>>>();
    k_hist<<<(N_EDGES + TB - 1) / TB, TB>>>(dst);
    k_dinv<<<(N_NODES + TB - 1) / TB, TB>>>();
    k_scan1<<<NBLK, SCAN_B>>>();
    k_scan2<<<1, 32>>>();
    k_scan3<<<(N_NODES + TB - 1) / TB, TB>>>();
    k_sort<<<(N_EDGES + TB - 1) / TB, TB>>>(src, dst);

    // layer 1: aggregate 128-d input first (linearity), then GEMM+bias+relu
    {
        int blocks = (N_NODES * 32 + TB - 1) / TB;
        k_agg<IN_DIM><<<blocks, TB>>>(x, xagg);
    }
    {
        dim3 grid((N_NODES + 127) / 128, 2);
        k_gemm<IN_DIM, true><<<grid, 256>>>(xagg, W1, b1, h1, N_NODES);
    }
    // layer 2
    {
        int blocks = (N_NODES * 32 + TB - 1) / TB;
        k_agg<HID><<<blocks, TB>>>(h1, h1agg);
    }
    {
        dim3 grid((N_NODES + 127) / 128, 2);
        k_gemm<HID, true><<<grid, 256>>>(h1agg, W2, b2, h2, N_NODES);
    }
    // output projection
    {
        int blocks = (N_NODES * 32 + TB - 1) / TB;
        k_out<<<blocks, TB>>>(h2, Wl, bl, out);
    }
}

// round 4
// speedup vs baseline: 1.7276x; 1.0079x over previous
#include <cuda_runtime.h>

#define N_NODES 50000
#define N_EDGES 600000
#define IN_DIM  128
#define HID     256

#define SCAN_B  1024
#define NBLK    ((N_NODES + SCAN_B - 1) / SCAN_B)   // 49

// ---------------- device scratch (no allocation allowed) ----------------
__device__ int   g_count[N_NODES];
__device__ int   g_fill[N_NODES];
__device__ int   g_rowptr[N_NODES + 1];
__device__ int   g_bsum[NBLK];
__device__ int   g_boff[NBLK];
__device__ float g_dinv[N_NODES];
__device__ int   g_col[N_EDGES];
__device__ float g_w[N_EDGES];
__device__ float g_xagg[(size_t)N_NODES * IN_DIM];
__device__ float g_h1[(size_t)N_NODES * HID];
__device__ float g_h1agg[(size_t)N_NODES * HID];

// ---------------- preprocessing ----------------
__global__ void k_init() {
    int i = blockIdx.x * blockDim.x + threadIdx.x;
    if (i < N_NODES) { g_count[i] = 0; g_fill[i] = 0; }
}

__global__ void k_hist(const int* __restrict__ dst) {
    int e = blockIdx.x * blockDim.x + threadIdx.x;
    if (e < N_EDGES) atomicAdd(&g_count[dst[e]], 1);
}

// block-level exclusive scan + per-block sums + dinv (count is final here)
__global__ void k_scan1() {
    __shared__ int warpsums[32];
    int b = blockIdx.x;
    int i = b * SCAN_B + threadIdx.x;
    int v = (i < N_NODES) ? g_count[i] : 0;
    if (i < N_NODES) g_dinv[i] = rsqrtf((float)v + 1.0f);
    int lane = threadIdx.x & 31, w = threadIdx.x >> 5;
    int p = v;
#pragma unroll
    for (int off = 1; off < 32; off <<= 1) {
        int t = __shfl_up_sync(0xFFFFFFFFu, p, off);
        if (lane >= off) p += t;
    }
    if (lane == 31) warpsums[w] = p;
    __syncthreads();
    if (w == 0) {
        int s = warpsums[lane];
#pragma unroll
        for (int off = 1; off < 32; off <<= 1) {
            int t = __shfl_up_sync(0xFFFFFFFFu, s, off);
            if (lane >= off) s += t;
        }
        warpsums[lane] = s;
    }
    __syncthreads();
    int excl = p - v + (w > 0 ? warpsums[w - 1] : 0);
    if (i < N_NODES) g_rowptr[i] = excl;              // block-local exclusive
    if (threadIdx.x == SCAN_B - 1) g_bsum[b] = excl + v;
}

// serial scan of 49 block sums; rowptr[N] stored so that +boff[last] = total
__global__ void k_scan2() {
    if (threadIdx.x == 0) {
        int acc = 0;
#pragma unroll
        for (int b = 0; b < NBLK; b++) { g_boff[b] = acc; acc += g_bsum[b]; }
        g_rowptr[N_NODES] = acc - g_boff[NBLK - 1];
    }
}

__global__ void k_sort(const int* __restrict__ src, const int* __restrict__ dst) {
    int e = blockIdx.x * blockDim.x + threadIdx.x;
    if (e >= N_EDGES) return;
    int d = dst[e];
    int s = src[e];
    int pos = g_rowptr[d] + g_boff[d >> 10] + atomicAdd(&g_fill[d], 1);
    g_col[pos] = s;
    g_w[pos]   = g_dinv[s];
}

// ---------------- aggregation: out[n] = dinv[n]*(sum_p w[p]*in[col[p]] + dinv[n]*in[n]) ----------------
template <int F>
__global__ void k_agg(const float* __restrict__ in, float* __restrict__ out) {
    int gwarp = (blockIdx.x * blockDim.x + threadIdx.x) >> 5;
    int lane  = threadIdx.x & 31;
    if (gwarp >= N_NODES) return;
    int beg = g_rowptr[gwarp]     + g_boff[gwarp >> 10];
    int end = g_rowptr[gwarp + 1] + g_boff[(gwarp + 1) >> 10];
    float dn = g_dinv[gwarp];
    constexpr int V = F / 128;   // float4s per lane
    float4 acc[V];
#pragma unroll
    for (int v = 0; v < V; v++) acc[v] = make_float4(0.f, 0.f, 0.f, 0.f);
    int p = beg;
    // 2-edge unroll for memory-level parallelism
    for (; p + 1 < end; p += 2) {
        int s0 = g_col[p],     s1 = g_col[p + 1];
        float w0 = g_w[p],     w1 = g_w[p + 1];
        const float4* r0 = (const float4*)(in + (size_t)s0 * F);
        const float4* r1 = (const float4*)(in + (size_t)s1 * F);
#pragma unroll
        for (int v = 0; v < V; v++) {
            float4 t0 = r0[lane + 32 * v];
            float4 t1 = r1[lane + 32 * v];
            acc[v].x += w0 * t0.x + w1 * t1.x;
            acc[v].y += w0 * t0.y + w1 * t1.y;
            acc[v].z += w0 * t0.z + w1 * t1.z;
            acc[v].w += w0 * t0.w + w1 * t1.w;
        }
    }
    if (p < end) {
        int s   = g_col[p];
        float w = g_w[p];
        const float4* rp = (const float4*)(in + (size_t)s * F);
#pragma unroll
        for (int v = 0; v < V; v++) {
            float4 t = rp[lane + 32 * v];
            acc[v].x += w * t.x; acc[v].y += w * t.y;
            acc[v].z += w * t.z; acc[v].w += w * t.w;
        }
    }
    const float4* sp = (const float4*)(in + (size_t)gwarp * F);
    float4* op = (float4*)(out + (size_t)gwarp * F);
#pragma unroll
    for (int v = 0; v < V; v++) {
        float4 t = sp[lane + 32 * v];
        float4 r;
        r.x = dn * (acc[v].x + dn * t.x);
        r.y = dn * (acc[v].y + dn * t.y);
        r.z = dn * (acc[v].z + dn * t.z);
        r.w = dn * (acc[v].w + dn * t.w);
        op[lane + 32 * v] = r;
    }
}

// ---------------- GEMM1: C[M,256] = relu(A[M,128] @ W[128,256] + b) ----------------
// BM=128, BN=128, BK=16, double-buffered, 256 threads, 8x8/thread
template <int K>
__global__ void __launch_bounds__(256, 2)
k_gemm1(const float* __restrict__ A, const float* __restrict__ W,
        const float* __restrict__ bias, float* __restrict__ C, int M) {
    __shared__ float As[2][16][128];
    __shared__ float Bs[2][16][128];
    const int bm = blockIdx.x * 128;
    const int bn = blockIdx.y * 128;
    const int tid = threadIdx.x;
    const int tx = tid % 16;
    const int ty = tid / 16;
    const int a_r = tid >> 1;
    const int a_c = (tid & 1) * 4;      // covers k-offsets a_c and a_c+8
    const int b_r = tid >> 4;
    const int b_c = (tid & 15) * 4;     // covers cols b_c and b_c+64

    float acc[8][8];
#pragma unroll
    for (int i = 0; i < 8; i++)
#pragma unroll
        for (int j = 0; j < 8; j++) acc[i][j] = 0.f;

    float4 ra0, ra1, rb0, rb1;
    const int m = bm + a_r;
    const bool mok = (m < M);

#define G1_LOAD(k0)                                                          \
    {                                                                        \
        ra0 = make_float4(0.f, 0.f, 0.f, 0.f);                               \
        ra1 = ra0;                                                           \
        if (mok) {                                                           \
            ra0 = *(const float4*)(A + (size_t)m * K + (k0) + a_c);          \
            ra1 = *(const float4*)(A + (size_t)m * K + (k0) + a_c + 8);      \
        }                                                                    \
        rb0 = *(const float4*)(W + (size_t)((k0) + b_r) * 256 + bn + b_c);   \
        rb1 = *(const float4*)(W + (size_t)((k0) + b_r) * 256 + bn + b_c + 64); \
    }
#define G1_STORE(buf)                                                        \
    {                                                                        \
        As[buf][a_c + 0][a_r] = ra0.x; As[buf][a_c + 1][a_r] = ra0.y;        \
        As[buf][a_c + 2][a_r] = ra0.z; As[buf][a_c + 3][a_r] = ra0.w;        \
        As[buf][a_c + 8][a_r] = ra1.x; As[buf][a_c + 9][a_r] = ra1.y;        \
        As[buf][a_c +10][a_r] = ra1.z; As[buf][a_c +11][a_r] = ra1.w;        \
        *(float4*)&Bs[buf][b_r][b_c]      = rb0;                             \
        *(float4*)&Bs[buf][b_r][b_c + 64] = rb1;                             \
    }

    G1_LOAD(0);
    G1_STORE(0);
    __syncthreads();
    constexpr int T = K / 16;
#pragma unroll
    for (int t = 0; t < T; t++) {
        if (t + 1 < T) G1_LOAD((t + 1) * 16);
        const int buf = t & 1;
#pragma unroll
        for (int kk = 0; kk < 16; kk++) {
            float a[8], b[8];
            float4 q;
            q = *(const float4*)&As[buf][kk][ty * 4];
            a[0] = q.x; a[1] = q.y; a[2] = q.z; a[3] = q.w;
            q = *(const float4*)&As[buf][kk][64 + ty * 4];
            a[4] = q.x; a[5] = q.y; a[6] = q.z; a[7] = q.w;
            q = *(const float4*)&Bs[buf][kk][tx * 4];
            b[0] = q.x; b[1] = q.y; b[2] = q.z; b[3] = q.w;
            q = *(const float4*)&Bs[buf][kk][64 + tx * 4];
            b[4] = q.x; b[5] = q.y; b[6] = q.z; b[7] = q.w;
#pragma unroll
            for (int i = 0; i < 8; i++)
#pragma unroll
                for (int j = 0; j < 8; j++) acc[i][j] += a[i] * b[j];
        }
        if (t + 1 < T) G1_STORE((t + 1) & 1);
        __syncthreads();
    }

#pragma unroll
    for (int i = 0; i < 8; i++) {
        int r = bm + ((i < 4) ? (ty * 4 + i) : (64 + ty * 4 + (i - 4)));
        if (r >= M) continue;
#pragma unroll
        for (int jh = 0; jh < 2; jh++) {
            int c0 = bn + jh * 64 + tx * 4;
            float4 v;
            float* a4 = &acc[i][jh * 4];
            v.x = fmaxf(a4[0] + bias[c0 + 0], 0.f);
            v.y = fmaxf(a4[1] + bias[c0 + 1], 0.f);
            v.z = fmaxf(a4[2] + bias[c0 + 2], 0.f);
            v.w = fmaxf(a4[3] + bias[c0 + 3], 0.f);
            *(float4*)(C + (size_t)r * 256 + c0) = v;
        }
    }
#undef G1_LOAD
#undef G1_STORE
}

// ---------------- GEMM2 + fused output projection ----------------
// out[r,:] = relu(A[r,:] @ W2 + b2) @ Wl + bl
// BM=64, BN=256 (full width -> no cross-block reduction), BK=16, double-buffered
__global__ void __launch_bounds__(256, 2)
k_gemm2(const float* __restrict__ A, const float* __restrict__ W,
        const float* __restrict__ bias, const float* __restrict__ Wl,
        const float* __restrict__ bl, float* __restrict__ out, int M) {
    __shared__ float As[2][16][64];
    __shared__ float Bs[2][16][256];
    const int bm = blockIdx.x * 64;
    const int tid = threadIdx.x;
    const int tx = tid & 31;           // lane
    const int ty = tid >> 5;           // warp
    const int a_r = tid >> 2;          // 0..63
    const int a_c = (tid & 3) * 4;     // 0,4,8,12
    const int b_r = tid >> 4;          // 0..15
    const int b_c = (tid & 15) * 4;    // cols b_c + {0,64,128,192}

    float acc[8][8];
#pragma unroll
    for (int i = 0; i < 8; i++)
#pragma unroll
        for (int j = 0; j < 8; j++) acc[i][j] = 0.f;

    float4 ra, rb0, rb1, rb2, rb3;
    const int m = bm + a_r;
    const bool mok = (m < M);

#define G2_LOAD(k0)                                                           \
    {                                                                         \
        ra = make_float4(0.f, 0.f, 0.f, 0.f);                                 \
        if (mok) ra = *(const float4*)(A + (size_t)m * 256 + (k0) + a_c);     \
        const float* wr = W + (size_t)((k0) + b_r) * 256;                     \
        rb0 = *(const float4*)(wr + b_c);                                     \
        rb1 = *(const float4*)(wr + b_c + 64);                                \
        rb2 = *(const float4*)(wr + b_c + 128);                               \
        rb3 = *(const float4*)(wr + b_c + 192);                               \
    }
#define G2_STORE(buf)                                                         \
    {                                                                         \
        As[buf][a_c + 0][a_r] = ra.x; As[buf][a_c + 1][a_r] = ra.y;           \
        As[buf][a_c + 2][a_r] = ra.z; As[buf][a_c + 3][a_r] = ra.w;           \
        *(float4*)&Bs[buf][b_r][b_c]       = rb0;                             \
        *(float4*)&Bs[buf][b_r][b_c + 64]  = rb1;                             \
        *(float4*)&Bs[buf][b_r][b_c + 128] = rb2;                             \
        *(float4*)&Bs[buf][b_r][b_c + 192] = rb3;                             \
    }

    G2_LOAD(0);
    G2_STORE(0);
    __syncthreads();
    constexpr int T = 256 / 16;
#pragma unroll
    for (int t = 0; t < T; t++) {
        if (t + 1 < T) G2_LOAD((t + 1) * 16);
        const int buf = t & 1;
#pragma unroll
        for (int kk = 0; kk < 16; kk++) {
            float a[8], b[8];
            float4 q;
            q = *(const float4*)&As[buf][kk][ty * 4];
            a[0] = q.x; a[1] = q.y; a[2] = q.z; a[3] = q.w;
            q = *(const float4*)&As[buf][kk][32 + ty * 4];
            a[4] = q.x; a[5] = q.y; a[6] = q.z; a[7] = q.w;
            q = *(const float4*)&Bs[buf][kk][tx * 4];
            b[0] = q.x; b[1] = q.y; b[2] = q.z; b[3] = q.w;
            q = *(const float4*)&Bs[buf][kk][128 + tx * 4];
            b[4] = q.x; b[5] = q.y; b[6] = q.z; b[7] = q.w;
#pragma unroll
            for (int i = 0; i < 8; i++)
#pragma unroll
                for (int j = 0; j < 8; j++) acc[i][j] += a[i] * b[j];
        }
        if (t + 1 < T) G2_STORE((t + 1) & 1);
        __syncthreads();
    }

    // fused epilogue: v = relu(acc + b2[c]); out[r] = sum_c v * Wl[c, :] + bl
    float wl0[8], wl1[8], bb[8];
#pragma unroll
    for (int jh = 0; jh < 2; jh++)
#pragma unroll
        for (int j = 0; j < 4; j++) {
            int c = jh * 128 + tx * 4 + j;
            wl0[jh * 4 + j] = Wl[c * 2 + 0];
            wl1[jh * 4 + j] = Wl[c * 2 + 1];
            bb[jh * 4 + j]  = bias[c];
        }
    float bl0 = bl[0], bl1 = bl[1];
#pragma unroll
    for (int i = 0; i < 8; i++) {
        int r = bm + ((i < 4) ? (ty * 4 + i) : (32 + ty * 4 + (i - 4)));
        float s0 = 0.f, s1 = 0.f;
#pragma unroll
        for (int j = 0; j < 8; j++) {
            float v = fmaxf(acc[i][j] + bb[j], 0.f);
            s0 += v * wl0[j];
            s1 += v * wl1[j];
        }
#pragma unroll
        for (int off = 16; off > 0; off >>= 1) {
            s0 += __shfl_down_sync(0xFFFFFFFFu, s0, off);
            s1 += __shfl_down_sync(0xFFFFFFFFu, s1, off);
        }
        if (tx == 0 && r < M) {
            out[(size_t)r * 2 + 0] = s0 + bl0;
            out[(size_t)r * 2 + 1] = s1 + bl1;
        }
    }
#undef G2_LOAD
#undef G2_STORE
}

// ---------------- launch ----------------
extern "C" void kernel_launch(void* const* d_in, const int* in_sizes, int n_in,
                              void* d_out, int out_size) {
    const float* x   = (const float*)d_in[0];
    const int*   ei  = (const int*)d_in[1];
    const float* W1  = (const float*)d_in[2];
    const float* b1  = (const float*)d_in[3];
    const float* W2  = (const float*)d_in[4];
    const float* b2  = (const float*)d_in[5];
    const float* Wl  = (const float*)d_in[6];
    const float* bl  = (const float*)d_in[7];
    float* out = (float*)d_out;

    const int* src = ei;            // edge_index[0, :]
    const int* dst = ei + N_EDGES;  // edge_index[1, :]

    float* xagg;  cudaGetSymbolAddress((void**)&xagg,  g_xagg);
    float* h1;    cudaGetSymbolAddress((void**)&h1,    g_h1);
    float* h1agg; cudaGetSymbolAddress((void**)&h1agg, g_h1agg);

    const int TB = 256;
    k_init<<<(N_NODES + TB - 1) / TB, TB>>>();                        // 0
    k_hist<<<(N_EDGES + TB - 1) / TB, TB>>>(dst);                     // 1
    k_scan1<<<NBLK, SCAN_B>>>();                                      // 2
    k_scan2<<<1, 32>>>();                                             // 3
    k_sort<<<(N_EDGES + TB - 1) / TB, TB>>>(src, dst);                // 4

    // layer 1: aggregate 128-d input first (linearity), then GEMM+bias+relu
    {
        int blocks = (N_NODES * 32 + TB - 1) / TB;
        k_agg<IN_DIM><<<blocks, TB>>>(x, xagg);                       // 5 (profiled)
    }
    {
        dim3 grid((N_NODES + 127) / 128, 2);
        k_gemm1<IN_DIM><<<grid, 256>>>(xagg, W1, b1, h1, N_NODES);    // 6
    }
    // layer 2
    {
        int blocks = (N_NODES * 32 + TB - 1) / TB;
        k_agg<HID><<<blocks, TB>>>(h1, h1agg);                        // 7
    }
    {
        int blocks = (N_NODES + 63) / 64;
        k_gemm2<<<blocks, 256>>>(h1agg, W2, b2, Wl, bl, out, N_NODES); // 8
    }
}

// round 5
// speedup vs baseline: 2.7691x; 1.6029x over previous
#include <cuda_runtime.h>
#include <cstdint>

#define N_NODES 50000
#define N_EDGES 600000
#define IN_DIM  128
#define HID     256

#define SCAN_B  1024
#define NBLK    ((N_NODES + SCAN_B - 1) / SCAN_B)   // 49

// ---------------- device scratch (no allocation allowed) ----------------
__device__ int   g_count[N_NODES];
__device__ int   g_fill[N_NODES];
__device__ int   g_rowptr[N_NODES + 1];
__device__ int   g_bsum[NBLK];
__device__ int   g_boff[NBLK];
__device__ float g_dinv[N_NODES];
__device__ int   g_col[N_EDGES];
__device__ float g_w[N_EDGES];
__device__ float g_xagg[(size_t)N_NODES * IN_DIM];
__device__ float g_h1[(size_t)N_NODES * HID];
__device__ float g_h1agg[(size_t)N_NODES * HID];
__device__ float g_h2[(size_t)N_NODES * HID];

// ---------------- preprocessing ----------------
__global__ void k_init() {
    int i = blockIdx.x * blockDim.x + threadIdx.x;
    if (i < N_NODES) { g_count[i] = 0; g_fill[i] = 0; }
}

__global__ void k_hist(const int* __restrict__ dst) {
    int e = blockIdx.x * blockDim.x + threadIdx.x;
    if (e < N_EDGES) atomicAdd(&g_count[dst[e]], 1);
}

// block-level exclusive scan + per-block sums + dinv (count is final here)
__global__ void k_scan1() {
    __shared__ int warpsums[32];
    int b = blockIdx.x;
    int i = b * SCAN_B + threadIdx.x;
    int v = (i < N_NODES) ? g_count[i] : 0;
    if (i < N_NODES) g_dinv[i] = rsqrtf((float)v + 1.0f);
    int lane = threadIdx.x & 31, w = threadIdx.x >> 5;
    int p = v;
#pragma unroll
    for (int off = 1; off < 32; off <<= 1) {
        int t = __shfl_up_sync(0xFFFFFFFFu, p, off);
        if (lane >= off) p += t;
    }
    if (lane == 31) warpsums[w] = p;
    __syncthreads();
    if (w == 0) {
        int s = warpsums[lane];
#pragma unroll
        for (int off = 1; off < 32; off <<= 1) {
            int t = __shfl_up_sync(0xFFFFFFFFu, s, off);
            if (lane >= off) s += t;
        }
        warpsums[lane] = s;
    }
    __syncthreads();
    int excl = p - v + (w > 0 ? warpsums[w - 1] : 0);
    if (i < N_NODES) g_rowptr[i] = excl;              // block-local exclusive
    if (threadIdx.x == SCAN_B - 1) g_bsum[b] = excl + v;
}

// single-warp pair-scan of 49 block sums -> g_boff (exclusive)
__global__ void k_scan2() {
    int lane = threadIdx.x;   // 32 threads
    int i0 = 2 * lane, i1 = 2 * lane + 1;
    int v0 = (i0 < NBLK) ? g_bsum[i0] : 0;
    int v1 = (i1 < NBLK) ? g_bsum[i1] : 0;
    int p = v0 + v1;
    int s = p;
#pragma unroll
    for (int off = 1; off < 32; off <<= 1) {
        int t = __shfl_up_sync(0xFFFFFFFFu, s, off);
        if (lane >= off) s += t;
    }
    int excl = s - p;
    if (i0 < NBLK) g_boff[i0] = excl;
    if (i1 < NBLK) g_boff[i1] = excl + v0;
    int total = __shfl_sync(0xFFFFFFFFu, s, 31);
    // rowptr[N] must satisfy: rowptr[N] + boff[N>>10] = total ; N>>10 = NBLK-1
    if (i0 == NBLK - 1) g_rowptr[N_NODES] = total - excl;
    if (i1 == NBLK - 1) g_rowptr[N_NODES] = total - (excl + v0);
}

__global__ void k_sort(const int* __restrict__ src, const int* __restrict__ dst) {
    int e = blockIdx.x * blockDim.x + threadIdx.x;
    if (e >= N_EDGES) return;
    int d = dst[e];
    int s = src[e];
    int pos = g_rowptr[d] + g_boff[d >> 10] + atomicAdd(&g_fill[d], 1);
    g_col[pos] = s;
    g_w[pos]   = g_dinv[s];
}

// ---------------- aggregation: out[n] = dinv[n]*(sum_p w[p]*in[col[p]] + dinv[n]*in[n]) ----------------
template <int F>
__global__ void k_agg(const float* __restrict__ in, float* __restrict__ out) {
    int gwarp = (blockIdx.x * blockDim.x + threadIdx.x) >> 5;
    int lane  = threadIdx.x & 31;
    if (gwarp >= N_NODES) return;
    int beg = g_rowptr[gwarp]     + g_boff[gwarp >> 10];
    int end = g_rowptr[gwarp + 1] + g_boff[(gwarp + 1) >> 10];
    float dn = g_dinv[gwarp];
    constexpr int V = F / 128;   // float4s per lane
    float4 acc[V];
#pragma unroll
    for (int v = 0; v < V; v++) acc[v] = make_float4(0.f, 0.f, 0.f, 0.f);
    int p = beg;
    for (; p + 1 < end; p += 2) {
        int s0 = g_col[p],     s1 = g_col[p + 1];
        float w0 = g_w[p],     w1 = g_w[p + 1];
        const float4* r0 = (const float4*)(in + (size_t)s0 * F);
        const float4* r1 = (const float4*)(in + (size_t)s1 * F);
#pragma unroll
        for (int v = 0; v < V; v++) {
            float4 t0 = r0[lane + 32 * v];
            float4 t1 = r1[lane + 32 * v];
            acc[v].x += w0 * t0.x + w1 * t1.x;
            acc[v].y += w0 * t0.y + w1 * t1.y;
            acc[v].z += w0 * t0.z + w1 * t1.z;
            acc[v].w += w0 * t0.w + w1 * t1.w;
        }
    }
    if (p < end) {
        int s   = g_col[p];
        float w = g_w[p];
        const float4* rp = (const float4*)(in + (size_t)s * F);
#pragma unroll
        for (int v = 0; v < V; v++) {
            float4 t = rp[lane + 32 * v];
            acc[v].x += w * t.x; acc[v].y += w * t.y;
            acc[v].z += w * t.z; acc[v].w += w * t.w;
        }
    }
    const float4* sp = (const float4*)(in + (size_t)gwarp * F);
    float4* op = (float4*)(out + (size_t)gwarp * F);
#pragma unroll
    for (int v = 0; v < V; v++) {
        float4 t = sp[lane + 32 * v];
        float4 r;
        r.x = dn * (acc[v].x + dn * t.x);
        r.y = dn * (acc[v].y + dn * t.y);
        r.z = dn * (acc[v].z + dn * t.z);
        r.w = dn * (acc[v].w + dn * t.w);
        op[lane + 32 * v] = r;
    }
}

// ---------------- TF32 tensor-core GEMM ----------------
// C[M,256] = relu(A[M,K] @ W[K,256] + b)
// BM=128, BN=128, BK=16, double-buffered. 8 warps as 2(M)x4(N); warp tile 64x32
// via m16n8k8 tf32 mma.sync (4 m-tiles x 4 n-tiles per warp).

__device__ __forceinline__ uint32_t f2tf32(float x) {
    uint32_t u;
    asm("cvt.rna.tf32.f32 %0, %1;" : "=r"(u) : "f"(x));
    return u;
}

__device__ __forceinline__ void mma_tf32(float c[4], uint32_t a0, uint32_t a1,
                                         uint32_t a2, uint32_t a3,
                                         uint32_t b0, uint32_t b1) {
    asm volatile(
        "mma.sync.aligned.m16n8k8.row.col.f32.tf32.tf32.f32 "
        "{%0,%1,%2,%3}, {%4,%5,%6,%7}, {%8,%9}, {%0,%1,%2,%3};"
        : "+f"(c[0]), "+f"(c[1]), "+f"(c[2]), "+f"(c[3])
        : "r"(a0), "r"(a1), "r"(a2), "r"(a3), "r"(b0), "r"(b1));
}

#define LDA 136   // 128 + 8 pad: conflict-free fragment loads

template <int K>
__global__ void __launch_bounds__(256, 2)
k_gemm_tc(const float* __restrict__ A, const float* __restrict__ W,
          const float* __restrict__ bias, float* __restrict__ C, int M) {
    __shared__ uint32_t As[2][16][LDA];   // [k][m], tf32 bits
    __shared__ uint32_t Bs[2][16][LDA];   // [k][n], tf32 bits
    const int bm = blockIdx.x * 128;
    const int bn = blockIdx.y * 128;
    const int tid  = threadIdx.x;
    const int lane = tid & 31;
    const int warp = tid >> 5;
    const int wm = warp >> 2;            // 0..1
    const int wn = warp & 3;             // 0..3
    const int g   = lane >> 2;           // 0..7
    const int tig = lane & 3;            // 0..3

    // global-load assignments
    const int a_r = tid >> 1;            // 0..127
    const int a_c = (tid & 1) * 4;       // 0 or 4 (also +8)
    const int b_r = tid >> 4;            // 0..15
    const int b_c = (tid & 15) * 4;      // 0..60 (also +64)

    float c[4][4][4];
#pragma unroll
    for (int i = 0; i < 4; i++)
#pragma unroll
        for (int j = 0; j < 4; j++)
#pragma unroll
            for (int r = 0; r < 4; r++) c[i][j][r] = 0.f;

    const int m = bm + a_r;
    const bool mok = (m < M);
    float4 ra0, ra1, rb0, rb1;

#define TC_LOAD(k0)                                                            \
    {                                                                          \
        ra0 = make_float4(0.f, 0.f, 0.f, 0.f);                                 \
        ra1 = ra0;                                                             \
        if (mok) {                                                             \
            ra0 = *(const float4*)(A + (size_t)m * K + (k0) + a_c);            \
            ra1 = *(const float4*)(A + (size_t)m * K + (k0) + a_c + 8);        \
        }                                                                      \
        rb0 = *(const float4*)(W + (size_t)((k0) + b_r) * 256 + bn + b_c);     \
        rb1 = *(const float4*)(W + (size_t)((k0) + b_r) * 256 + bn + b_c + 64);\
    }
#define TC_STORE(buf)                                                          \
    {                                                                          \
        As[buf][a_c + 0][a_r] = f2tf32(ra0.x);                                 \
        As[buf][a_c + 1][a_r] = f2tf32(ra0.y);                                 \
        As[buf][a_c + 2][a_r] = f2tf32(ra0.z);                                 \
        As[buf][a_c + 3][a_r] = f2tf32(ra0.w);                                 \
        As[buf][a_c + 8][a_r] = f2tf32(ra1.x);                                 \
        As[buf][a_c + 9][a_r] = f2tf32(ra1.y);                                 \
        As[buf][a_c +10][a_r] = f2tf32(ra1.z);                                 \
        As[buf][a_c +11][a_r] = f2tf32(ra1.w);                                 \
        Bs[buf][b_r][b_c + 0]  = f2tf32(rb0.x);                                \
        Bs[buf][b_r][b_c + 1]  = f2tf32(rb0.y);                                \
        Bs[buf][b_r][b_c + 2]  = f2tf32(rb0.z);                                \
        Bs[buf][b_r][b_c + 3]  = f2tf32(rb0.w);                                \
        Bs[buf][b_r][b_c + 64] = f2tf32(rb1.x);                                \
        Bs[buf][b_r][b_c + 65] = f2tf32(rb1.y);                                \
        Bs[buf][b_r][b_c + 66] = f2tf32(rb1.z);                                \
        Bs[buf][b_r][b_c + 67] = f2tf32(rb1.w);                                \
    }

    TC_LOAD(0);
    TC_STORE(0);
    __syncthreads();
    constexpr int T = K / 16;
#pragma unroll
    for (int t = 0; t < T; t++) {
        if (t + 1 < T) TC_LOAD((t + 1) * 16);
        const int buf = t & 1;
#pragma unroll
        for (int kk = 0; kk < 2; kk++) {
            const int k8 = kk * 8;
            uint32_t af[4][4], bf[4][2];
#pragma unroll
            for (int mt = 0; mt < 4; mt++) {
                int mb = wm * 64 + mt * 16;
                af[mt][0] = As[buf][k8 + tig][mb + g];
                af[mt][1] = As[buf][k8 + tig][mb + g + 8];
                af[mt][2] = As[buf][k8 + tig + 4][mb + g];
                af[mt][3] = As[buf][k8 + tig + 4][mb + g + 8];
            }
#pragma unroll
            for (int nt = 0; nt < 4; nt++) {
                int nb = wn * 32 + nt * 8;
                bf[nt][0] = Bs[buf][k8 + tig][nb + g];
                bf[nt][1] = Bs[buf][k8 + tig + 4][nb + g];
            }
#pragma unroll
            for (int mt = 0; mt < 4; mt++)
#pragma unroll
                for (int nt = 0; nt < 4; nt++)
                    mma_tf32(c[mt][nt], af[mt][0], af[mt][1], af[mt][2],
                             af[mt][3], bf[nt][0], bf[nt][1]);
        }
        if (t + 1 < T) TC_STORE((t + 1) & 1);
        __syncthreads();
    }

    // epilogue: bias + relu, float2 stores (c0,c1 / c2,c3 are adjacent cols)
#pragma unroll
    for (int nt = 0; nt < 4; nt++) {
        int col = bn + wn * 32 + nt * 8 + tig * 2;
        float bb0 = bias[col], bb1 = bias[col + 1];
#pragma unroll
        for (int mt = 0; mt < 4; mt++) {
            int row0 = bm + wm * 64 + mt * 16 + g;
            int row1 = row0 + 8;
            if (row0 < M) {
                float2 v;
                v.x = fmaxf(c[mt][nt][0] + bb0, 0.f);
                v.y = fmaxf(c[mt][nt][1] + bb1, 0.f);
                *(float2*)(C + (size_t)row0 * 256 + col) = v;
            }
            if (row1 < M) {
                float2 v;
                v.x = fmaxf(c[mt][nt][2] + bb0, 0.f);
                v.y = fmaxf(c[mt][nt][3] + bb1, 0.f);
                *(float2*)(C + (size_t)row1 * 256 + col) = v;
            }
        }
    }
#undef TC_LOAD
#undef TC_STORE
}

// ---------------- final projection: out[N,2] = h2 @ Wl + bl ----------------
__global__ void k_out(const float* __restrict__ h2, const float* __restrict__ Wl,
                      const float* __restrict__ bl, float* __restrict__ out) {
    int gwarp = (blockIdx.x * blockDim.x + threadIdx.x) >> 5;
    int lane  = threadIdx.x & 31;
    if (gwarp >= N_NODES) return;
    const float4* rp = (const float4*)(h2 + (size_t)gwarp * HID);
    float s0 = 0.f, s1 = 0.f;
#pragma unroll
    for (int v = 0; v < 2; v++) {
        float4 t = rp[lane + 32 * v];
        int k = (lane + 32 * v) * 4;
        s0 += t.x * Wl[(k + 0) * 2 + 0] + t.y * Wl[(k + 1) * 2 + 0]
            + t.z * Wl[(k + 2) * 2 + 0] + t.w * Wl[(k + 3) * 2 + 0];
        s1 += t.x * Wl[(k + 0) * 2 + 1] + t.y * Wl[(k + 1) * 2 + 1]
            + t.z * Wl[(k + 2) * 2 + 1] + t.w * Wl[(k + 3) * 2 + 1];
    }
#pragma unroll
    for (int off = 16; off > 0; off >>= 1) {
        s0 += __shfl_down_sync(0xFFFFFFFFu, s0, off);
        s1 += __shfl_down_sync(0xFFFFFFFFu, s1, off);
    }
    if (lane == 0) {
        out[(size_t)gwarp * 2 + 0] = s0 + bl[0];
        out[(size_t)gwarp * 2 + 1] = s1 + bl[1];
    }
}

// ---------------- launch ----------------
extern "C" void kernel_launch(void* const* d_in, const int* in_sizes, int n_in,
                              void* d_out, int out_size) {
    const float* x   = (const float*)d_in[0];
    const int*   ei  = (const int*)d_in[1];
    const float* W1  = (const float*)d_in[2];
    const float* b1  = (const float*)d_in[3];
    const float* W2  = (const float*)d_in[4];
    const float* b2  = (const float*)d_in[5];
    const float* Wl  = (const float*)d_in[6];
    const float* bl  = (const float*)d_in[7];
    float* out = (float*)d_out;

    const int* src = ei;            // edge_index[0, :]
    const int* dst = ei + N_EDGES;  // edge_index[1, :]

    float* xagg;  cudaGetSymbolAddress((void**)&xagg,  g_xagg);
    float* h1;    cudaGetSymbolAddress((void**)&h1,    g_h1);
    float* h1agg; cudaGetSymbolAddress((void**)&h1agg, g_h1agg);
    float* h2;    cudaGetSymbolAddress((void**)&h2,    g_h2);

    const int TB = 256;
    k_init<<<(N_NODES + TB - 1) / TB, TB>>>();
    k_hist<<<(N_EDGES + TB - 1) / TB, TB>>>(dst);
    k_scan1<<<NBLK, SCAN_B>>>();
    k_scan2<<<1, 32>>>();
    k_sort<<<(N_EDGES + TB - 1) / TB, TB>>>(src, dst);

    // layer 1: aggregate 128-d input first (linearity), then GEMM+bias+relu
    {
        int blocks = (N_NODES * 32 + TB - 1) / TB;
        k_agg<IN_DIM><<<blocks, TB>>>(x, xagg);
    }
    {
        dim3 grid((N_NODES + 127) / 128, 2);
        k_gemm_tc<IN_DIM><<<grid, 256>>>(xagg, W1, b1, h1, N_NODES);
    }
    // layer 2
    {
        int blocks = (N_NODES * 32 + TB - 1) / TB;
        k_agg<HID><<<blocks, TB>>>(h1, h1agg);
    }
    {
        dim3 grid((N_NODES + 127) / 128, 2);
        k_gemm_tc<HID><<<grid, 256>>>(h1agg, W2, b2, h2, N_NODES);
    }
    // output projection
    {
        int blocks = (N_NODES * 32 + TB - 1) / TB;
        k_out<<<blocks, TB>>>(h2, Wl, bl, out);
    }
}

// round 8
// speedup vs baseline: 3.2262x; 1.1651x over previous
#include <cuda_runtime.h>
#include <cstdint>

#define N_NODES 50000
#define N_EDGES 600000
#define IN_DIM  128
#define HID     256

#define SCAN_B  1024
#define NBLK    ((N_NODES + SCAN_B - 1) / SCAN_B)   // 49

// ---------------- device scratch (no allocation allowed) ----------------
__device__ int   g_count[N_NODES];
__device__ int   g_fill[N_NODES];
__device__ int   g_rowptr[N_NODES + 1];
__device__ int   g_bsum[NBLK];
__device__ int   g_boff[NBLK];
__device__ int   g_ticket;          // zero-initialized; reset after each use
__device__ float g_dinv[N_NODES];
__device__ int   g_col[N_EDGES];
__device__ float g_w[N_EDGES];
__device__ float g_xagg[(size_t)N_NODES * IN_DIM];
__device__ float g_h1[(size_t)N_NODES * HID];
__device__ float g_h1agg[(size_t)N_NODES * HID];

// ---------------- preprocessing ----------------
__global__ void k_init() {
    int i = blockIdx.x * blockDim.x + threadIdx.x;
    if (i < N_NODES) { g_count[i] = 0; g_fill[i] = 0; }
}

__global__ void k_hist(const int* __restrict__ dst) {
    int e = blockIdx.x * blockDim.x + threadIdx.x;
    if (e < N_EDGES) atomicAdd(&g_count[dst[e]], 1);
}

// block-local exclusive scan + dinv; last block to finish scans the block sums
__global__ void k_scan1() {
    __shared__ int warpsums[32];
    __shared__ int s_last;
    int b = blockIdx.x;
    int i = b * SCAN_B + threadIdx.x;
    int v = (i < N_NODES) ? g_count[i] : 0;
    if (i < N_NODES) g_dinv[i] = rsqrtf((float)v + 1.0f);
    int lane = threadIdx.x & 31, w = threadIdx.x >> 5;
    int p = v;
#pragma unroll
    for (int off = 1; off < 32; off <<= 1) {
        int t = __shfl_up_sync(0xFFFFFFFFu, p, off);
        if (lane >= off) p += t;
    }
    if (lane == 31) warpsums[w] = p;
    __syncthreads();
    if (w == 0) {
        int s = warpsums[lane];
#pragma unroll
        for (int off = 1; off < 32; off <<= 1) {
            int t = __shfl_up_sync(0xFFFFFFFFu, s, off);
            if (lane >= off) s += t;
        }
        warpsums[lane] = s;
    }
    __syncthreads();
    int excl = p - v + (w > 0 ? warpsums[w - 1] : 0);
    if (i < N_NODES) g_rowptr[i] = excl;              // block-local exclusive
    if (threadIdx.x == SCAN_B - 1) g_bsum[b] = excl + v;

    // ---- last-block ticket: scan the 49 block sums in-place ----
    __threadfence();
    __syncthreads();
    if (threadIdx.x == 0) {
        int t = atomicAdd(&g_ticket, 1);
        s_last = (t == NBLK - 1) ? 1 : 0;
    }
    __syncthreads();
    if (s_last) {
        if (threadIdx.x == 0) g_ticket = 0;           // reset for graph replay
        if (threadIdx.x < 32) {
            __threadfence();
            int l = threadIdx.x;
            int i0 = 2 * l, i1 = 2 * l + 1;
            int v0 = (i0 < NBLK) ? g_bsum[i0] : 0;
            int v1 = (i1 < NBLK) ? g_bsum[i1] : 0;
            int pr = v0 + v1;
            int s = pr;
#pragma unroll
            for (int off = 1; off < 32; off <<= 1) {
                int t = __shfl_up_sync(0xFFFFFFFFu, s, off);
                if (l >= off) s += t;
            }
            int e2 = s - pr;
            if (i0 < NBLK) g_boff[i0] = e2;
            if (i1 < NBLK) g_boff[i1] = e2 + v0;
            int total = __shfl_sync(0xFFFFFFFFu, s, 31);
            // rowptr[N] + boff[NBLK-1] must equal total
            if (i0 == NBLK - 1) g_rowptr[N_NODES] = total - e2;
            if (i1 == NBLK - 1) g_rowptr[N_NODES] = total - (e2 + v0);
        }
    }
}

__global__ void k_sort(const int* __restrict__ src, const int* __restrict__ dst) {
    int e = blockIdx.x * blockDim.x + threadIdx.x;
    if (e >= N_EDGES) return;
    int d = dst[e];
    int s = src[e];
    int pos = g_rowptr[d] + g_boff[d >> 10] + atomicAdd(&g_fill[d], 1);
    g_col[pos] = s;
    g_w[pos]   = g_dinv[s];
}

// ---------------- aggregation ----------------
// out[n] = dinv[n]*(sum_p w[p]*in[col[p]] + dinv[n]*in[n])
// one warp per (node, 128-col half): F=128 -> 1 warp/node, F=256 -> 2 warps/node
template <int F>
__global__ void k_agg(const float* __restrict__ in, float* __restrict__ out) {
    constexpr int H = F / 128;
    constexpr int RS = F / 4;   // row stride in float4
    int gw   = (blockIdx.x * blockDim.x + threadIdx.x) >> 5;
    int lane = threadIdx.x & 31;
    int node = gw / H;
    int half = gw - node * H;
    if (node >= N_NODES) return;
    int beg = g_rowptr[node]     + g_boff[node >> 10];
    int end = g_rowptr[node + 1] + g_boff[(node + 1) >> 10];
    float dn = g_dinv[node];
    const float4* base = (const float4*)in + (size_t)half * 32 + lane;
    float4 acc = make_float4(0.f, 0.f, 0.f, 0.f);
    int p = beg;
    for (; p + 3 < end; p += 4) {
        int s0 = g_col[p],   s1 = g_col[p+1], s2 = g_col[p+2], s3 = g_col[p+3];
        float w0 = g_w[p],   w1 = g_w[p+1],   w2 = g_w[p+2],   w3 = g_w[p+3];
        float4 t0 = base[(size_t)s0 * RS];
        float4 t1 = base[(size_t)s1 * RS];
        float4 t2 = base[(size_t)s2 * RS];
        float4 t3 = base[(size_t)s3 * RS];
        acc.x += w0*t0.x + w1*t1.x + w2*t2.x + w3*t3.x;
        acc.y += w0*t0.y + w1*t1.y + w2*t2.y + w3*t3.y;
        acc.z += w0*t0.z + w1*t1.z + w2*t2.z + w3*t3.z;
        acc.w += w0*t0.w + w1*t1.w + w2*t2.w + w3*t3.w;
    }
    for (; p < end; p++) {
        int s = g_col[p];
        float wv = g_w[p];
        float4 t = base[(size_t)s * RS];
        acc.x += wv*t.x; acc.y += wv*t.y; acc.z += wv*t.z; acc.w += wv*t.w;
    }
    float4 t = base[(size_t)node * RS];
    float4 r;
    r.x = dn * (acc.x + dn * t.x);
    r.y = dn * (acc.y + dn * t.y);
    r.z = dn * (acc.z + dn * t.z);
    r.w = dn * (acc.w + dn * t.w);
    *((float4*)out + (size_t)node * RS + half * 32 + lane) = r;
}

// ---------------- TF32 helpers ----------------
__device__ __forceinline__ uint32_t f2tf32(float x) {
    uint32_t u;
    asm("cvt.rna.tf32.f32 %0, %1;" : "=r"(u) : "f"(x));
    return u;
}

__device__ __forceinline__ void mma_tf32(float c[4], uint32_t a0, uint32_t a1,
                                         uint32_t a2, uint32_t a3,
                                         uint32_t b0, uint32_t b1) {
    asm volatile(
        "mma.sync.aligned.m16n8k8.row.col.f32.tf32.tf32.f32 "
        "{%0,%1,%2,%3}, {%4,%5,%6,%7}, {%8,%9}, {%0,%1,%2,%3};"
        : "+f"(c[0]), "+f"(c[1]), "+f"(c[2]), "+f"(c[3])
        : "r"(a0), "r"(a1), "r"(a2), "r"(a3), "r"(b0), "r"(b1));
}

// ---------------- GEMM1 (TF32 TC): h1 = relu(xagg @ W1 + b1) ----------------
// BM=128, BN=128, BK=16, double-buffered. 8 warps 2x4, warp tile 64x32.
#define LDA 136

template <int K>
__global__ void __launch_bounds__(256, 2)
k_gemm_tc(const float* __restrict__ A, const float* __restrict__ W,
          const float* __restrict__ bias, float* __restrict__ C, int M) {
    __shared__ uint32_t As[2][16][LDA];
    __shared__ uint32_t Bs[2][16][LDA];
    const int bm = blockIdx.x * 128;
    const int bn = blockIdx.y * 128;
    const int tid  = threadIdx.x;
    const int lane = tid & 31;
    const int warp = tid >> 5;
    const int wm = warp >> 2;
    const int wn = warp & 3;
    const int g   = lane >> 2;
    const int tig = lane & 3;
    const int a_r = tid >> 1;
    const int a_c = (tid & 1) * 4;
    const int b_r = tid >> 4;
    const int b_c = (tid & 15) * 4;

    float c[4][4][4];
#pragma unroll
    for (int i = 0; i < 4; i++)
#pragma unroll
        for (int j = 0; j < 4; j++)
#pragma unroll
            for (int r = 0; r < 4; r++) c[i][j][r] = 0.f;

    const int m = bm + a_r;
    const bool mok = (m < M);
    float4 ra0, ra1, rb0, rb1;

#define TC_LOAD(k0)                                                            \
    {                                                                          \
        ra0 = make_float4(0.f, 0.f, 0.f, 0.f);                                 \
        ra1 = ra0;                                                             \
        if (mok) {                                                             \
            ra0 = *(const float4*)(A + (size_t)m * K + (k0) + a_c);            \
            ra1 = *(const float4*)(A + (size_t)m * K + (k0) + a_c + 8);        \
        }                                                                      \
        rb0 = *(const float4*)(W + (size_t)((k0) + b_r) * 256 + bn + b_c);     \
        rb1 = *(const float4*)(W + (size_t)((k0) + b_r) * 256 + bn + b_c + 64);\
    }
#define TC_STORE(buf)                                                          \
    {                                                                          \
        As[buf][a_c + 0][a_r] = f2tf32(ra0.x);                                 \
        As[buf][a_c + 1][a_r] = f2tf32(ra0.y);                                 \
        As[buf][a_c + 2][a_r] = f2tf32(ra0.z);                                 \
        As[buf][a_c + 3][a_r] = f2tf32(ra0.w);                                 \
        As[buf][a_c + 8][a_r] = f2tf32(ra1.x);                                 \
        As[buf][a_c + 9][a_r] = f2tf32(ra1.y);                                 \
        As[buf][a_c +10][a_r] = f2tf32(ra1.z);                                 \
        As[buf][a_c +11][a_r] = f2tf32(ra1.w);                                 \
        Bs[buf][b_r][b_c + 0]  = f2tf32(rb0.x);                                \
        Bs[buf][b_r][b_c + 1]  = f2tf32(rb0.y);                                \
        Bs[buf][b_r][b_c + 2]  = f2tf32(rb0.z);                                \
        Bs[buf][b_r][b_c + 3]  = f2tf32(rb0.w);                                \
        Bs[buf][b_r][b_c + 64] = f2tf32(rb1.x);                                \
        Bs[buf][b_r][b_c + 65] = f2tf32(rb1.y);                                \
        Bs[buf][b_r][b_c + 66] = f2tf32(rb1.z);                                \
        Bs[buf][b_r][b_c + 67] = f2tf32(rb1.w);                                \
    }

    TC_LOAD(0);
    TC_STORE(0);
    __syncthreads();
    constexpr int T = K / 16;
#pragma unroll
    for (int t = 0; t < T; t++) {
        if (t + 1 < T) TC_LOAD((t + 1) * 16);
        const int buf = t & 1;
#pragma unroll
        for (int kk = 0; kk < 2; kk++) {
            const int k8 = kk * 8;
            uint32_t af[4][4], bf[4][2];
#pragma unroll
            for (int mt = 0; mt < 4; mt++) {
                int mb = wm * 64 + mt * 16;
                af[mt][0] = As[buf][k8 + tig][mb + g];
                af[mt][1] = As[buf][k8 + tig][mb + g + 8];
                af[mt][2] = As[buf][k8 + tig + 4][mb + g];
                af[mt][3] = As[buf][k8 + tig + 4][mb + g + 8];
            }
#pragma unroll
            for (int nt = 0; nt < 4; nt++) {
                int nb = wn * 32 + nt * 8;
                bf[nt][0] = Bs[buf][k8 + tig][nb + g];
                bf[nt][1] = Bs[buf][k8 + tig + 4][nb + g];
            }
#pragma unroll
            for (int mt = 0; mt < 4; mt++)
#pragma unroll
                for (int nt = 0; nt < 4; nt++)
                    mma_tf32(c[mt][nt], af[mt][0], af[mt][1], af[mt][2],
                             af[mt][3], bf[nt][0], bf[nt][1]);
        }
        if (t + 1 < T) TC_STORE((t + 1) & 1);
        __syncthreads();
    }

#pragma unroll
    for (int nt = 0; nt < 4; nt++) {
        int col = bn + wn * 32 + nt * 8 + tig * 2;
        float bb0 = bias[col], bb1 = bias[col + 1];
#pragma unroll
        for (int mt = 0; mt < 4; mt++) {
            int row0 = bm + wm * 64 + mt * 16 + g;
            int row1 = row0 + 8;
            if (row0 < M) {
                float2 v;
                v.x = fmaxf(c[mt][nt][0] + bb0, 0.f);
                v.y = fmaxf(c[mt][nt][1] + bb1, 0.f);
                *(float2*)(C + (size_t)row0 * 256 + col) = v;
            }
            if (row1 < M) {
                float2 v;
                v.x = fmaxf(c[mt][nt][2] + bb0, 0.f);
                v.y = fmaxf(c[mt][nt][3] + bb1, 0.f);
                *(float2*)(C + (size_t)row1 * 256 + col) = v;
            }
        }
    }
#undef TC_LOAD
#undef TC_STORE
}

// ---------------- GEMM2 + fused 256->2 projection ----------------
// out[r,:] = relu(A[r,:] @ W2 + b2) @ Wl + bl
// BM=64, BN=256 (full width, no cross-block reduction), BK=8, double-buffered.
// 8 warps, warp n-slice of 32 cols; warp tile 64x32 (4 m-tiles x 4 n-tiles).
__global__ void __launch_bounds__(256, 2)
k_gemm2f(const float* __restrict__ A, const float* __restrict__ W,
         const float* __restrict__ b2, const float* __restrict__ Wl,
         const float* __restrict__ bl, float* __restrict__ out, int M) {
    __shared__ uint32_t As[2][8][72];
    __shared__ uint32_t Bs[2][8][264];
    __shared__ float red[8][64][2];
    const int bm = blockIdx.x * 64;
    const int tid  = threadIdx.x;
    const int lane = tid & 31;
    const int wn   = tid >> 5;          // 0..7, 32-col slice
    const int g    = lane >> 2;
    const int tig  = lane & 3;
    const int a_r  = tid >> 2;          // 0..63
    const int a_c  = (tid & 3) * 2;     // 0,2,4,6
    const int b_r  = tid >> 5;          // 0..7
    const int b_c  = (tid & 31) * 4;    // +0, +128

    float c[4][4][4];
#pragma unroll
    for (int i = 0; i < 4; i++)
#pragma unroll
        for (int j = 0; j < 4; j++)
#pragma unroll
            for (int r = 0; r < 4; r++) c[i][j][r] = 0.f;

    const int m = bm + a_r;
    const bool mok = (m < M);
    float2 ra;
    float4 rb0, rb1;

#define G2_LOAD(k0)                                                            \
    {                                                                          \
        ra = make_float2(0.f, 0.f);                                            \
        if (mok) ra = *(const float2*)(A + (size_t)m * 256 + (k0) + a_c);      \
        const float* wr = W + (size_t)((k0) + b_r) * 256;                      \
        rb0 = *(const float4*)(wr + b_c);                                      \
        rb1 = *(const float4*)(wr + b_c + 128);                                \
    }
#define G2_STORE(buf)                                                          \
    {                                                                          \
        As[buf][a_c + 0][a_r] = f2tf32(ra.x);                                  \
        As[buf][a_c + 1][a_r] = f2tf32(ra.y);                                  \
        Bs[buf][b_r][b_c + 0]   = f2tf32(rb0.x);                               \
        Bs[buf][b_r][b_c + 1]   = f2tf32(rb0.y);                               \
        Bs[buf][b_r][b_c + 2]   = f2tf32(rb0.z);                               \
        Bs[buf][b_r][b_c + 3]   = f2tf32(rb0.w);                               \
        Bs[buf][b_r][b_c + 128] = f2tf32(rb1.x);                               \
        Bs[buf][b_r][b_c + 129] = f2tf32(rb1.y);                               \
        Bs[buf][b_r][b_c + 130] = f2tf32(rb1.z);                               \
        Bs[buf][b_r][b_c + 131] = f2tf32(rb1.w);                               \
    }

    G2_LOAD(0);
    G2_STORE(0);
    __syncthreads();
    constexpr int T = 256 / 8;
#pragma unroll
    for (int t = 0; t < T; t++) {
        if (t + 1 < T) G2_LOAD((t + 1) * 8);
        const int buf = t & 1;
        uint32_t af[4][4], bf[4][2];
#pragma unroll
        for (int mt = 0; mt < 4; mt++) {
            int mb = mt * 16;
            af[mt][0] = As[buf][tig][mb + g];
            af[mt][1] = As[buf][tig][mb + g + 8];
            af[mt][2] = As[buf][tig + 4][mb + g];
            af[mt][3] = As[buf][tig + 4][mb + g + 8];
        }
#pragma unroll
        for (int nt = 0; nt < 4; nt++) {
            int nb = wn * 32 + nt * 8;
            bf[nt][0] = Bs[buf][tig][nb + g];
            bf[nt][1] = Bs[buf][tig + 4][nb + g];
        }
#pragma unroll
        for (int mt = 0; mt < 4; mt++)
#pragma unroll
            for (int nt = 0; nt < 4; nt++)
                mma_tf32(c[mt][nt], af[mt][0], af[mt][1], af[mt][2], af[mt][3],
                         bf[nt][0], bf[nt][1]);
        if (t + 1 < T) G2_STORE((t + 1) & 1);
        __syncthreads();
    }

    // fused epilogue: v = relu(acc + b2); partial = v @ Wl; reduce tig, warps
    float wl0[8], wl1[8], bb[8];
#pragma unroll
    for (int nt = 0; nt < 4; nt++)
#pragma unroll
        for (int j = 0; j < 2; j++) {
            int col = wn * 32 + nt * 8 + tig * 2 + j;
            int idx = nt * 2 + j;
            bb[idx]  = b2[col];
            wl0[idx] = Wl[col * 2 + 0];
            wl1[idx] = Wl[col * 2 + 1];
        }
#pragma unroll
    for (int mt = 0; mt < 4; mt++) {
        float r0s0 = 0.f, r0s1 = 0.f, r1s0 = 0.f, r1s1 = 0.f;
#pragma unroll
        for (int nt = 0; nt < 4; nt++) {
            float v0 = fmaxf(c[mt][nt][0] + bb[nt * 2 + 0], 0.f);
            float v1 = fmaxf(c[mt][nt][1] + bb[nt * 2 + 1], 0.f);
            float v2 = fmaxf(c[mt][nt][2] + bb[nt * 2 + 0], 0.f);
            float v3 = fmaxf(c[mt][nt][3] + bb[nt * 2 + 1], 0.f);
            r0s0 += v0 * wl0[nt * 2] + v1 * wl0[nt * 2 + 1];
            r0s1 += v0 * wl1[nt * 2] + v1 * wl1[nt * 2 + 1];
            r1s0 += v2 * wl0[nt * 2] + v3 * wl0[nt * 2 + 1];
            r1s1 += v2 * wl1[nt * 2] + v3 * wl1[nt * 2 + 1];
        }
#pragma unroll
        for (int off = 1; off <= 2; off <<= 1) {
            r0s0 += __shfl_xor_sync(0xFFFFFFFFu, r0s0, off);
            r0s1 += __shfl_xor_sync(0xFFFFFFFFu, r0s1, off);
            r1s0 += __shfl_xor_sync(0xFFFFFFFFu, r1s0, off);
            r1s1 += __shfl_xor_sync(0xFFFFFFFFu, r1s1, off);
        }
        if (tig == 0) {
            red[wn][mt * 16 + g][0]     = r0s0;
            red[wn][mt * 16 + g][1]     = r0s1;
            red[wn][mt * 16 + 8 + g][0] = r1s0;
            red[wn][mt * 16 + 8 + g][1] = r1s1;
        }
    }
    __syncthreads();
    if (tid < 128) {
        int row = tid >> 1, d = tid & 1;
        float s = bl[d];
#pragma unroll
        for (int w = 0; w < 8; w++) s += red[w][row][d];
        int r = bm + row;
        if (r < M) out[(size_t)r * 2 + d] = s;
    }
#undef G2_LOAD
#undef G2_STORE
}

// ---------------- launch ----------------
extern "C" void kernel_launch(void* const* d_in, const int* in_sizes, int n_in,
                              void* d_out, int out_size) {
    const float* x   = (const float*)d_in[0];
    const int*   ei  = (const int*)d_in[1];
    const float* W1  = (const float*)d_in[2];
    const float* b1  = (const float*)d_in[3];
    const float* W2  = (const float*)d_in[4];
    const float* b2  = (const float*)d_in[5];
    const float* Wl  = (const float*)d_in[6];
    const float* bl  = (const float*)d_in[7];
    float* out = (float*)d_out;

    const int* src = ei;            // edge_index[0, :]
    const int* dst = ei + N_EDGES;  // edge_index[1, :]

    float* xagg;  cudaGetSymbolAddress((void**)&xagg,  g_xagg);
    float* h1;    cudaGetSymbolAddress((void**)&h1,    g_h1);
    float* h1agg; cudaGetSymbolAddress((void**)&h1agg, g_h1agg);

    const int TB = 256;
    k_init<<<(N_NODES + TB - 1) / TB, TB>>>();
    k_hist<<<(N_EDGES + TB - 1) / TB, TB>>>(dst);
    k_scan1<<<NBLK, SCAN_B>>>();
    k_sort<<<(N_EDGES + TB - 1) / TB, TB>>>(src, dst);

    // layer 1
    {
        int warps = N_NODES;                       // 1 warp/node (128 cols)
        int blocks = (warps * 32 + TB - 1) / TB;
        k_agg<IN_DIM><<<blocks, TB>>>(x, xagg);
    }
    {
        dim3 grid((N_NODES + 127) / 128, 2);
        k_gemm_tc<IN_DIM><<<grid, 256>>>(xagg, W1, b1, h1, N_NODES);
    }
    // layer 2 + fused output projection
    {
        int warps = N_NODES * 2;                   // 2 warps/node (256 cols)
        int blocks = (warps * 32 + TB - 1) / TB;
        k_agg<HID><<<blocks, TB>>>(h1, h1agg);
    }
    {
        int blocks = (N_NODES + 63) / 64;
        k_gemm2f<<<blocks, 256>>>(h1agg, W2, b2, Wl, bl, out, N_NODES);
    }
}